// round 12
// baseline (speedup 1.0000x reference)
#include <cuda_runtime.h>
#include <math.h>
#include <stdint.h>

#define Nn 50000
#define Ee 250000
#define Bb 128
#define Dd 302
#define Qq 600
#define Cc 2000
#define NEG_SLOPE 0.2f

// ---------------- scratch (device globals; no allocation allowed) ----------
__device__ float g_h[(size_t)Nn * Dd];     // GEMM output (pre-aggregation h)
__device__ float g_o[(size_t)Nn * Dd];     // agg output (next GEMM input / pooling)
__device__ float g_as[Nn], g_ad[Nn], g_s[Nn];
__device__ float g_asp[3][Nn], g_adp[3][Nn];
__device__ int   g_cnt[Nn];
__device__ int   g_cur[Nn];
__device__ int   g_rowptr[Nn + 1];
__device__ int   g_bsum[256];
__device__ int   g_csrc[Ee + Nn];
__device__ float g_qp[Bb * Dd];
__device__ float g_pool[Bb * Dd];

// ---------------- helpers ---------------------------------------------------
__device__ __forceinline__ float lrelu(float x) { return x > 0.f ? x : NEG_SLOPE * x; }

__device__ __forceinline__ int lower_bound_i(const int* a, int n, int v) {
    int lo = 0, hi = n;
    while (lo < hi) { int m = (lo + hi) >> 1; if (a[m] < v) lo = m + 1; else hi = m; }
    return lo;
}

__device__ __forceinline__ float tf32f(float f) {
    uint32_t r; asm("cvt.rna.tf32.f32 %0, %1;" : "=r"(r) : "f"(f));
    return __uint_as_float(r);
}

#define MMA_TF32(cr, a, b) \
    asm volatile("mma.sync.aligned.m16n8k8.row.col.f32.tf32.tf32.f32 " \
        "{%0,%1,%2,%3}, {%4,%5,%6,%7}, {%8,%9}, {%0,%1,%2,%3};" \
        : "+f"((cr)[0]), "+f"((cr)[1]), "+f"((cr)[2]), "+f"((cr)[3]) \
        : "r"((a)[0]), "r"((a)[1]), "r"((a)[2]), "r"((a)[3]), \
          "r"((b)[0]), "r"((b)[1]))

#define CP_ASYNC8(dst_smem, src_ptr, sz) \
    asm volatile("cp.async.ca.shared.global [%0], [%1], 8, %2;" \
        :: "r"(dst_smem), "l"(src_ptr), "r"(sz))
#define CP_COMMIT() asm volatile("cp.async.commit_group;" ::: "memory")
#define CP_WAIT1()  asm volatile("cp.async.wait_group 1;" ::: "memory")

// ---------------- CSR build --------------------------------------------------
__global__ void zero_k() {
    int i = blockIdx.x * blockDim.x + threadIdx.x;
    if (i < Nn) { g_cnt[i] = 0; g_cur[i] = 0; }
}

__global__ void count_k(const int* __restrict__ edges) {
    int i = blockIdx.x * blockDim.x + threadIdx.x;
    if (i >= Ee + Nn) return;
    int dst = (i < Ee) ? edges[Ee + i] : (i - Ee);
    atomicAdd(&g_cnt[dst], 1);
}

// parallel scan: per-block exclusive scan + block totals
__global__ void scan1_k() {
    __shared__ int sh[256];
    int tid = threadIdx.x;
    int i = blockIdx.x * 256 + tid;
    int v = (i < Nn) ? g_cnt[i] : 0;
    sh[tid] = v;
    __syncthreads();
    #pragma unroll
    for (int off = 1; off < 256; off <<= 1) {
        int t = (tid >= off) ? sh[tid - off] : 0;
        __syncthreads();
        sh[tid] += t;
        __syncthreads();
    }
    if (i <= Nn) g_rowptr[i] = sh[tid] - v;   // exclusive within block
    if (tid == 255) g_bsum[blockIdx.x] = sh[255];
}

__global__ void scan2_k(int nblk) {
    __shared__ int sh[256];
    int tid = threadIdx.x;
    int v = (tid < nblk) ? g_bsum[tid] : 0;
    sh[tid] = v;
    __syncthreads();
    #pragma unroll
    for (int off = 1; off < 256; off <<= 1) {
        int t = (tid >= off) ? sh[tid - off] : 0;
        __syncthreads();
        sh[tid] += t;
        __syncthreads();
    }
    if (tid < nblk) g_bsum[tid] = sh[tid] - v;  // exclusive block offsets
    if (tid == 255) g_rowptr[Nn] = sh[255];
}

__global__ void scan3_k() {
    int i = blockIdx.x * 256 + threadIdx.x;
    if (i < Nn) g_rowptr[i] += g_bsum[blockIdx.x];
}

__global__ void fill_k(const int* __restrict__ edges) {
    int i = blockIdx.x * blockDim.x + threadIdx.x;
    if (i >= Ee + Nn) return;
    int src, dst;
    if (i < Ee) { src = edges[i]; dst = edges[Ee + i]; }
    else        { src = dst = i - Ee; }
    int p = g_rowptr[dst] + atomicAdd(&g_cur[dst], 1);
    g_csrc[p] = src;
}

// ---------------- tf32 mma GEMM: raw fp32 staging, in-register hi/lo split --
// C[M,302] = A[M,302] @ theta[302,302]^T. CTA tile 128x128x32, cp.async
// double-buffered (dynamic smem). 8 warps = 2(m) x 4(n); warp tile 64x32.
// 3-term split. Fully-OOB n-warps skip MMA. Epilogue fuses attention dots.
#define BMt 128
#define BNt 128
#define BKt 32
#define SWd 36              // padded row stride (32 k + 4 pad) -> conflict-free
#define NIT 10              // ceil(302/32)
#define STGF (BMt * SWd)    // 4608 floats per stage buffer
// dynamic smem (floats): SA[2][STGF] SB[2][STGF] s_as[128] s_ad[128] s_pas[512] s_pad[512]
#define OFF_SB   (2 * STGF)
#define OFF_ATTS (4 * STGF)
#define OFF_ATTD (OFF_ATTS + 128)
#define OFF_PAS  (OFF_ATTS + 256)
#define OFF_PAD  (OFF_PAS + 512)
#define GEMM_SMEM ((4 * STGF + 256 + 1024) * 4)

__global__ __launch_bounds__(256, 2) void gemm_mma_k(const float* __restrict__ A,
                                                     const float* __restrict__ W,
                                                     float* __restrict__ C,
                                                     const float* __restrict__ att_s,
                                                     const float* __restrict__ att_d) {
    extern __shared__ float sm[];
    float* s_as  = sm + OFF_ATTS;
    float* s_ad  = sm + OFF_ATTD;
    float* s_pas = sm + OFF_PAS;
    float* s_pad = sm + OFF_PAD;

    int tid = threadIdx.x;
    int wid = tid >> 5, lane = tid & 31;
    int g = lane >> 2, t = lane & 3;
    int m0 = blockIdx.y * BMt, n0 = blockIdx.x * BNt;
    int wm = (wid >> 2) * 64;
    int wn = (wid & 3) * 32;
    const bool active = (n0 + wn) < Dd;   // warp-uniform column validity

    if (tid < 128) {
        int c = n0 + tid;
        s_as[tid] = (c < Dd) ? att_s[c] : 0.f;
        s_ad[tid] = (c < Dd) ? att_d[c] : 0.f;
    }

    float c[4][4][4];
    #pragma unroll
    for (int i = 0; i < 4; i++)
        #pragma unroll
        for (int j = 0; j < 4; j++)
            #pragma unroll
            for (int f = 0; f < 4; f++) c[i][j][f] = 0.f;

    // staging: elem = tid + e*256 over 2048 float2 slots; row = elem>>4, col2 = elem&15
    auto stage = [&](int s, int k0) {
        float* sa = sm + s * STGF;
        float* sb = sm + OFF_SB + s * STGF;
        #pragma unroll
        for (int e = 0; e < 8; e++) {
            int elem = tid + e * 256;
            int row = elem >> 4, c2 = elem & 15;
            int gm = m0 + row, gk = k0 + 2 * c2;
            bool ok = (gm < Nn) && (gk < Dd);
            const float* src = ok ? (A + (size_t)gm * Dd + gk) : A;
            uint32_t dst = (uint32_t)__cvta_generic_to_shared(&sa[row * SWd + 2 * c2]);
            CP_ASYNC8(dst, src, ok ? 8u : 0u);
        }
        #pragma unroll
        for (int e = 0; e < 8; e++) {
            int elem = tid + e * 256;
            int row = elem >> 4, c2 = elem & 15;
            int gn = n0 + row, gk = k0 + 2 * c2;
            bool ok = (gn < Dd) && (gk < Dd);
            const float* src = ok ? (W + (size_t)gn * Dd + gk) : W;
            uint32_t dst = (uint32_t)__cvta_generic_to_shared(&sb[row * SWd + 2 * c2]);
            CP_ASYNC8(dst, src, ok ? 8u : 0u);
        }
    };

    stage(0, 0);
    CP_COMMIT();

    for (int it = 0; it < NIT; it++) {
        if (it + 1 < NIT) stage((it + 1) & 1, (it + 1) * BKt);
        CP_COMMIT();
        CP_WAIT1();
        __syncthreads();

        if (active) {
            const float* sa = sm + (it & 1) * STGF;
            const float* sb = sm + OFF_SB + (it & 1) * STGF;

            #pragma unroll
            for (int kk = 0; kk < 4; kk++) {
                int kb = kk * 8;
                uint32_t bh[4][2], bl[4][2];
                #pragma unroll
                for (int nt = 0; nt < 4; nt++) {
                    int nr = wn + nt * 8 + g;
                    float w0 = sb[nr * SWd + kb + t];
                    float w1 = sb[nr * SWd + kb + t + 4];
                    float h0 = tf32f(w0), h1 = tf32f(w1);
                    bh[nt][0] = __float_as_uint(h0);
                    bh[nt][1] = __float_as_uint(h1);
                    bl[nt][0] = __float_as_uint(tf32f(w0 - h0));
                    bl[nt][1] = __float_as_uint(tf32f(w1 - h1));
                }
                #pragma unroll
                for (int mt = 0; mt < 4; mt++) {
                    int mr = wm + mt * 16 + g;
                    float a0 = sa[mr * SWd + kb + t];
                    float a1 = sa[(mr + 8) * SWd + kb + t];
                    float a2 = sa[mr * SWd + kb + t + 4];
                    float a3 = sa[(mr + 8) * SWd + kb + t + 4];
                    float h0 = tf32f(a0), h1 = tf32f(a1), h2 = tf32f(a2), h3 = tf32f(a3);
                    uint32_t ah[4], al[4];
                    ah[0] = __float_as_uint(h0); ah[1] = __float_as_uint(h1);
                    ah[2] = __float_as_uint(h2); ah[3] = __float_as_uint(h3);
                    al[0] = __float_as_uint(tf32f(a0 - h0));
                    al[1] = __float_as_uint(tf32f(a1 - h1));
                    al[2] = __float_as_uint(tf32f(a2 - h2));
                    al[3] = __float_as_uint(tf32f(a3 - h3));
                    #pragma unroll
                    for (int nt = 0; nt < 4; nt++) {
                        MMA_TF32(c[mt][nt], ah, bh[nt]);
                        MMA_TF32(c[mt][nt], ah, bl[nt]);
                        MMA_TF32(c[mt][nt], al, bh[nt]);
                    }
                }
            }
        }
        __syncthreads();
    }

    // epilogue: store C + fused partial attention dots
    #pragma unroll
    for (int mt = 0; mt < 4; mt++) {
        int row = m0 + wm + mt * 16 + g;
        float ps = 0.f, pd = 0.f, qs = 0.f, qd = 0.f;
        #pragma unroll
        for (int nt = 0; nt < 4; nt++) {
            int cn = wn + nt * 8 + 2 * t;       // local col in [0,128)
            int col = n0 + cn;
            if (col < Dd) {
                if (row < Nn)
                    *(float2*)(C + (size_t)row * Dd + col) =
                        make_float2(c[mt][nt][0], c[mt][nt][1]);
                if (row + 8 < Nn)
                    *(float2*)(C + (size_t)(row + 8) * Dd + col) =
                        make_float2(c[mt][nt][2], c[mt][nt][3]);
            }
            float a0 = s_as[cn], a1 = s_as[cn + 1];
            float d0 = s_ad[cn], d1 = s_ad[cn + 1];
            ps += c[mt][nt][0] * a0 + c[mt][nt][1] * a1;
            pd += c[mt][nt][0] * d0 + c[mt][nt][1] * d1;
            qs += c[mt][nt][2] * a0 + c[mt][nt][3] * a1;
            qd += c[mt][nt][2] * d0 + c[mt][nt][3] * d1;
        }
        #pragma unroll
        for (int o = 1; o <= 2; o <<= 1) {
            ps += __shfl_xor_sync(0xffffffffu, ps, o);
            pd += __shfl_xor_sync(0xffffffffu, pd, o);
            qs += __shfl_xor_sync(0xffffffffu, qs, o);
            qd += __shfl_xor_sync(0xffffffffu, qd, o);
        }
        if (t == 0) {
            int i1 = wm + mt * 16 + g;
            int nw = wid & 3;
            s_pas[nw * 128 + i1] = ps;  s_pad[nw * 128 + i1] = pd;
            s_pas[nw * 128 + i1 + 8] = qs;  s_pad[nw * 128 + i1 + 8] = qd;
        }
    }
    __syncthreads();
    if (tid < 128) {
        int row = m0 + tid;
        if (row < Nn)
            g_asp[blockIdx.x][row] = s_pas[tid] + s_pas[128 + tid] +
                                     s_pas[256 + tid] + s_pas[384 + tid];
    } else {
        int i = tid - 128;
        int row = m0 + i;
        if (row < Nn)
            g_adp[blockIdx.x][row] = s_pad[i] + s_pad[128 + i] +
                                     s_pad[256 + i] + s_pad[384 + i];
    }
}

__global__ void combine_k() {
    int i = blockIdx.x * blockDim.x + threadIdx.x;
    if (i < Nn) {
        g_as[i] = g_asp[0][i] + g_asp[1][i] + g_asp[2][i];
        g_ad[i] = g_adp[0][i] + g_adp[1][i] + g_adp[2][i];
    }
}

// ---------------- fused edge softmax + aggregation (warp per dst) -----------
// mode 1 additionally computes the pooling score g_s.
__global__ void agg_k(const float* __restrict__ h,
                      const float* __restrict__ bias,
                      float* __restrict__ outp,
                      const int* __restrict__ batch, int mode) {
    int w = (blockIdx.x * blockDim.x + threadIdx.x) >> 5;
    int lane = threadIdx.x & 31;
    if (w >= Nn) return;
    int beg = g_rowptr[w], end = g_rowptr[w + 1];
    float ad = g_ad[w];

    // online softmax (max + denominator in one pass)
    float m = -3.4e38f, den = 0.f;
    for (int j = beg + lane; j < end; j += 32) {
        float e = lrelu(g_as[g_csrc[j]] + ad);
        if (e > m) { den = den * __expf(m - e) + 1.f; m = e; }
        else den += __expf(e - m);
    }
    #pragma unroll
    for (int o = 16; o; o >>= 1) {
        float mo = __shfl_xor_sync(0xffffffffu, m, o);
        float eo = __shfl_xor_sync(0xffffffffu, den, o);
        float mn = fmaxf(m, mo);
        den = den * __expf(m - mn) + eo * __expf(mo - mn);
        m = mn;
    }
    float inv = 1.f / den;

    float acc[10];
    #pragma unroll
    for (int i = 0; i < 10; i++) acc[i] = 0.f;

    for (int base = beg; base < end; base += 32) {
        int j = base + lane;
        float wt = 0.f; int src = 0;
        if (j < end) {
            src = g_csrc[j];
            wt = __expf(lrelu(g_as[src] + ad) - m) * inv;
        }
        int cnt = min(32, end - base);
        for (int u = 0; u < cnt; u++) {
            float wu = __shfl_sync(0xffffffffu, wt, u);
            int   su = __shfl_sync(0xffffffffu, src, u);
            const float* hr = h + (size_t)su * Dd;
            #pragma unroll
            for (int i = 0; i < 9; i++) acc[i] += wu * hr[lane + i * 32];
            int cc = lane + 288;
            if (cc < Dd) acc[9] += wu * hr[cc];
        }
    }

    if (mode == 0) {
        #pragma unroll
        for (int i = 0; i < 10; i++) {
            int cc = lane + i * 32;
            if (cc < Dd) {
                float v = acc[i] + bias[cc];
                outp[(size_t)w * Dd + cc] = v > 0.f ? v : 0.f;
            }
        }
    } else {
        int b = batch[w];
        const float* qr = g_qp + b * Dd;
        float s = 0.f;
        #pragma unroll
        for (int i = 0; i < 10; i++) {
            int cc = lane + i * 32;
            if (cc < Dd) {
                float v = acc[i] + bias[cc];
                v = v > 0.f ? v : 0.f;
                outp[(size_t)w * Dd + cc] = v;
                s += v * qr[cc];
            }
        }
        #pragma unroll
        for (int o = 16; o; o >>= 1) s += __shfl_xor_sync(0xffffffffu, s, o);
        if (lane == 0) g_s[w] = s * 0.04082482904638630f;  // 1/sqrt(600)
    }
}

// ---------------- qp = query @ attW  [B,D] ----------------------------------
__global__ void qp_k(const float* __restrict__ query, const float* __restrict__ attW) {
    int b = blockIdx.x;
    __shared__ float q[Qq];
    for (int i = threadIdx.x; i < Qq; i += blockDim.x) q[i] = query[(size_t)b * Qq + i];
    __syncthreads();
    for (int d = threadIdx.x; d < Dd; d += blockDim.x) {
        float acc = 0.f;
        for (int qi = 0; qi < Qq; qi++) acc += q[qi] * attW[(size_t)qi * Dd + d];
        g_qp[b * Dd + d] = acc;
    }
}

// ---------------- block-per-graph softmax pooling (batch is sorted) ---------
__global__ __launch_bounds__(256) void pool_k(const float* __restrict__ h,
                                              const int* __restrict__ batch) {
    int b = blockIdx.x;
    int tid = threadIdx.x, wid = tid >> 5, lane = tid & 31;
    __shared__ float red[256];
    __shared__ float s_acc[8][304];
    int start = lower_bound_i(batch, Nn, b);
    int end   = lower_bound_i(batch, Nn, b + 1);

    float m = -3.4e38f;
    for (int n = start + tid; n < end; n += 256) m = fmaxf(m, g_s[n]);
    red[tid] = m; __syncthreads();
    for (int o = 128; o; o >>= 1) { if (tid < o) red[tid] = fmaxf(red[tid], red[tid + o]); __syncthreads(); }
    m = red[0]; __syncthreads();

    float ds = 0.f;
    for (int n = start + tid; n < end; n += 256) ds += __expf(g_s[n] - m);
    red[tid] = ds; __syncthreads();
    for (int o = 128; o; o >>= 1) { if (tid < o) red[tid] += red[tid + o]; __syncthreads(); }
    float total = red[0];
    float inv = (total > 0.f) ? 1.f / total : 0.f;
    __syncthreads();

    float acc[10];
    #pragma unroll
    for (int i = 0; i < 10; i++) acc[i] = 0.f;
    for (int r = start + wid; r < end; r += 8) {
        float wt = __expf(g_s[r] - m) * inv;
        const float* hr = h + (size_t)r * Dd;
        #pragma unroll
        for (int i = 0; i < 9; i++) acc[i] += wt * hr[lane + i * 32];
        int cc = lane + 288;
        if (cc < Dd) acc[9] += wt * hr[cc];
    }
    #pragma unroll
    for (int i = 0; i < 10; i++) {
        int cc = lane + i * 32;
        if (cc < Dd) s_acc[wid][cc] = acc[i];
    }
    __syncthreads();
    for (int cc = tid; cc < Dd; cc += 256) {
        float v = 0.f;
        #pragma unroll
        for (int u = 0; u < 8; u++) v += s_acc[u][cc];
        g_pool[b * Dd + cc] = v > 0.f ? v : 0.f;   // ReLU fused
    }
}

// ---------------- final: out = relu(pooled) @ lin_w^T + lin_b ---------------
#define FINAL_SMEM (128 * 303 * 4)
__global__ __launch_bounds__(512) void final_k(const float* __restrict__ lin_w,
                                               const float* __restrict__ lin_b,
                                               float* __restrict__ out) {
    extern __shared__ float ps[];   // [128][303]
    int tid = threadIdx.x;
    for (int i = tid; i < Bb * Dd; i += 512) {
        int bb = i / Dd, k = i - bb * Dd;
        ps[bb * 303 + k] = g_pool[i];
    }
    __syncthreads();
    int w = tid >> 5, lane = tid & 31;
    int c = blockIdx.x * 16 + w;
    const float* wr = lin_w + (size_t)c * Dd;
    float a0 = 0.f, a1 = 0.f, a2 = 0.f, a3 = 0.f;
    for (int k = 0; k < Dd; k++) {
        float wv = wr[k];
        a0 += wv * ps[lane * 303 + k];
        a1 += wv * ps[(lane + 32) * 303 + k];
        a2 += wv * ps[(lane + 64) * 303 + k];
        a3 += wv * ps[(lane + 96) * 303 + k];
    }
    float lb = lin_b[c];
    out[(size_t)lane * Cc + c]        = a0 + lb;
    out[(size_t)(lane + 32) * Cc + c] = a1 + lb;
    out[(size_t)(lane + 64) * Cc + c] = a2 + lb;
    out[(size_t)(lane + 96) * Cc + c] = a3 + lb;
}

// ---------------- launch -----------------------------------------------------
extern "C" void kernel_launch(void* const* d_in, const int* in_sizes, int n_in,
                              void* d_out, int out_size) {
    const float* x        = (const float*)d_in[0];
    const int*   edges    = (const int*)  d_in[1];
    const float* query    = (const float*)d_in[2];
    const int*   batch    = (const int*)  d_in[3];
    const float* theta    = (const float*)d_in[4];
    const float* att_src  = (const float*)d_in[5];
    const float* att_dst  = (const float*)d_in[6];
    const float* gat_bias = (const float*)d_in[7];
    const float* attW     = (const float*)d_in[8];
    const float* lin_w    = (const float*)d_in[9];
    const float* lin_b    = (const float*)d_in[10];
    float* out = (float*)d_out;

    float *p_h, *p_o;
    cudaGetSymbolAddress((void**)&p_h, g_h);
    cudaGetSymbolAddress((void**)&p_o, g_o);

    cudaFuncSetAttribute(gemm_mma_k, cudaFuncAttributeMaxDynamicSharedMemorySize, GEMM_SMEM);
    cudaFuncSetAttribute(final_k, cudaFuncAttributeMaxDynamicSharedMemorySize, FINAL_SMEM);

    dim3 ggrid((Dd + BNt - 1) / BNt, (Nn + BMt - 1) / BMt);
    int wgrid = (Nn * 32 + 255) / 256;
    int cgrid = (Nn + 255) / 256;
    int sblk = (Nn + 255) / 256;   // 196 scan blocks

    // CSR build (parallel scan)
    zero_k<<<cgrid, 256>>>();
    count_k<<<(Ee + Nn + 255) / 256, 256>>>(edges);
    scan1_k<<<sblk, 256>>>();
    scan2_k<<<1, 256>>>(sblk);
    scan3_k<<<sblk, 256>>>();
    fill_k<<<(Ee + Nn + 255) / 256, 256>>>(edges);

    // layer 1 (input = raw x)
    gemm_mma_k<<<ggrid, 256, GEMM_SMEM>>>(x, theta, p_h, att_src, att_dst);
    combine_k<<<cgrid, 256>>>();
    agg_k<<<wgrid, 256>>>(p_h, gat_bias, p_o, batch, 0);
    // layer 2
    gemm_mma_k<<<ggrid, 256, GEMM_SMEM>>>(p_o, theta, p_h, att_src, att_dst);
    combine_k<<<cgrid, 256>>>();
    agg_k<<<wgrid, 256>>>(p_h, gat_bias, p_o, batch, 0);
    // layer 3 (fuses pooling score)
    gemm_mma_k<<<ggrid, 256, GEMM_SMEM>>>(p_o, theta, p_h, att_src, att_dst);
    combine_k<<<cgrid, 256>>>();
    qp_k<<<Bb, 384>>>(query, attW);
    agg_k<<<wgrid, 256>>>(p_h, gat_bias, p_o, batch, 1);

    pool_k<<<Bb, 256>>>(p_o, batch);
    final_k<<<Cc / 16, 512, FINAL_SMEM>>>(lin_w, lin_b, out);
}

// round 13
// speedup vs baseline: 1.4583x; 1.4583x over previous
#include <cuda_runtime.h>
#include <math.h>
#include <stdint.h>

#define Nn 50000
#define Ee 250000
#define Bb 128
#define Dd 302
#define Qq 600
#define Cc 2000
#define NEG_SLOPE 0.2f

// ---------------- scratch (device globals; no allocation allowed) ----------
__device__ float g_h[(size_t)Nn * Dd];     // GEMM output (pre-aggregation h)
__device__ float g_o[(size_t)Nn * Dd];     // agg output (next GEMM input / pooling)
__device__ float g_as[Nn], g_ad[Nn], g_s[Nn];
__device__ float g_asp[3][Nn], g_adp[3][Nn];
__device__ int   g_cnt[Nn];
__device__ int   g_cur[Nn];
__device__ int   g_rowptr[Nn + 1];
__device__ int   g_bsum[256];
__device__ int   g_csrc[Ee + Nn];
__device__ float g_qp[Bb * Dd];
__device__ float g_pool[Bb * Dd];

// ---------------- helpers ---------------------------------------------------
__device__ __forceinline__ float lrelu(float x) { return x > 0.f ? x : NEG_SLOPE * x; }

__device__ __forceinline__ int lower_bound_i(const int* a, int n, int v) {
    int lo = 0, hi = n;
    while (lo < hi) { int m = (lo + hi) >> 1; if (a[m] < v) lo = m + 1; else hi = m; }
    return lo;
}

__device__ __forceinline__ float tf32f(float f) {
    uint32_t r; asm("cvt.rna.tf32.f32 %0, %1;" : "=r"(r) : "f"(f));
    return __uint_as_float(r);
}

#define MMA_TF32(cr, a, b) \
    asm volatile("mma.sync.aligned.m16n8k8.row.col.f32.tf32.tf32.f32 " \
        "{%0,%1,%2,%3}, {%4,%5,%6,%7}, {%8,%9}, {%0,%1,%2,%3};" \
        : "+f"((cr)[0]), "+f"((cr)[1]), "+f"((cr)[2]), "+f"((cr)[3]) \
        : "r"((a)[0]), "r"((a)[1]), "r"((a)[2]), "r"((a)[3]), \
          "r"((b)[0]), "r"((b)[1]))

#define CP_ASYNC8(dst_smem, src_ptr, sz) \
    asm volatile("cp.async.ca.shared.global [%0], [%1], 8, %2;" \
        :: "r"(dst_smem), "l"(src_ptr), "r"(sz))
#define CP_COMMIT() asm volatile("cp.async.commit_group;" ::: "memory")
#define CP_WAIT0()  asm volatile("cp.async.wait_group 0;" ::: "memory")

// ---------------- CSR build --------------------------------------------------
__global__ void zero_k() {
    int i = blockIdx.x * blockDim.x + threadIdx.x;
    if (i < Nn) { g_cnt[i] = 0; g_cur[i] = 0; }
}

__global__ void count_k(const int* __restrict__ edges) {
    int i = blockIdx.x * blockDim.x + threadIdx.x;
    if (i >= Ee + Nn) return;
    int dst = (i < Ee) ? edges[Ee + i] : (i - Ee);
    atomicAdd(&g_cnt[dst], 1);
}

// parallel scan: per-block exclusive scan + block totals
__global__ void scan1_k() {
    __shared__ int sh[256];
    int tid = threadIdx.x;
    int i = blockIdx.x * 256 + tid;
    int v = (i < Nn) ? g_cnt[i] : 0;
    sh[tid] = v;
    __syncthreads();
    #pragma unroll
    for (int off = 1; off < 256; off <<= 1) {
        int t = (tid >= off) ? sh[tid - off] : 0;
        __syncthreads();
        sh[tid] += t;
        __syncthreads();
    }
    if (i <= Nn) g_rowptr[i] = sh[tid] - v;   // exclusive within block
    if (tid == 255) g_bsum[blockIdx.x] = sh[255];
}

__global__ void scan2_k(int nblk) {
    __shared__ int sh[256];
    int tid = threadIdx.x;
    int v = (tid < nblk) ? g_bsum[tid] : 0;
    sh[tid] = v;
    __syncthreads();
    #pragma unroll
    for (int off = 1; off < 256; off <<= 1) {
        int t = (tid >= off) ? sh[tid - off] : 0;
        __syncthreads();
        sh[tid] += t;
        __syncthreads();
    }
    if (tid < nblk) g_bsum[tid] = sh[tid] - v;  // exclusive block offsets
    if (tid == 255) g_rowptr[Nn] = sh[255];
}

__global__ void scan3_k() {
    int i = blockIdx.x * 256 + threadIdx.x;
    if (i < Nn) g_rowptr[i] += g_bsum[blockIdx.x];
}

__global__ void fill_k(const int* __restrict__ edges) {
    int i = blockIdx.x * blockDim.x + threadIdx.x;
    if (i >= Ee + Nn) return;
    int src, dst;
    if (i < Ee) { src = edges[i]; dst = edges[Ee + i]; }
    else        { src = dst = i - Ee; }
    int p = g_rowptr[dst] + atomicAdd(&g_cur[dst], 1);
    g_csrc[p] = src;
}

// ---------------- tf32 mma GEMM: raw fp32 staging, in-register hi/lo split --
// C[M,302] = A[M,302] @ theta[302,302]^T. CTA tile 128x128x16, cp.async
// double-buffered (static smem, 2 CTA/SM). 8 warps = 2(m) x 4(n); warp tile
// 64x32. 3-term split. Fully-OOB n-warps skip MMA. One barrier per k-iter.
// Epilogue fuses attention dots.
#define BMt 128
#define BNt 128
#define BKt 16
#define SWd 20
#define NIT 19              // ceil(302/16)

__global__ __launch_bounds__(256, 2) void gemm_mma_k(const float* __restrict__ A,
                                                     const float* __restrict__ W,
                                                     float* __restrict__ C,
                                                     const float* __restrict__ att_s,
                                                     const float* __restrict__ att_d) {
    __shared__ float Sa[2][BMt * SWd];
    __shared__ float Sw[2][BNt * SWd];
    __shared__ float s_as[128], s_ad[128];
    __shared__ float s_pas[512], s_pad[512];

    int tid = threadIdx.x;
    int wid = tid >> 5, lane = tid & 31;
    int g = lane >> 2, t = lane & 3;
    int m0 = blockIdx.y * BMt, n0 = blockIdx.x * BNt;
    int wm = (wid >> 2) * 64;
    int wn = (wid & 3) * 32;
    const bool active = (n0 + wn) < Dd;   // warp-uniform column validity

    if (tid < 128) {
        int c = n0 + tid;
        s_as[tid] = (c < Dd) ? att_s[c] : 0.f;
        s_ad[tid] = (c < Dd) ? att_d[c] : 0.f;
    }

    float c[4][4][4];
    #pragma unroll
    for (int i = 0; i < 4; i++)
        #pragma unroll
        for (int j = 0; j < 4; j++)
            #pragma unroll
            for (int f = 0; f < 4; f++) c[i][j][f] = 0.f;

    int srow = tid >> 3;   // 0..31
    int sc2  = tid & 7;    // float2 column index

    auto stage = [&](int s, int k0) {
        #pragma unroll
        for (int e = 0; e < 4; e++) {
            int row = srow + e * 32;
            int gm = m0 + row, gk = k0 + 2 * sc2;
            bool ok = (gm < Nn) && (gk < Dd);
            const float* src = ok ? (A + (size_t)gm * Dd + gk) : A;
            uint32_t dst = (uint32_t)__cvta_generic_to_shared(&Sa[s][row * SWd + 2 * sc2]);
            CP_ASYNC8(dst, src, ok ? 8u : 0u);
        }
        #pragma unroll
        for (int e = 0; e < 4; e++) {
            int row = srow + e * 32;
            int gn = n0 + row, gk = k0 + 2 * sc2;
            bool ok = (gn < Dd) && (gk < Dd);
            const float* src = ok ? (W + (size_t)gn * Dd + gk) : W;
            uint32_t dst = (uint32_t)__cvta_generic_to_shared(&Sw[s][row * SWd + 2 * sc2]);
            CP_ASYNC8(dst, src, ok ? 8u : 0u);
        }
    };

    stage(0, 0);
    CP_COMMIT();

    for (int it = 0; it < NIT; it++) {
        CP_WAIT0();            // stage(it) complete (sole outstanding group)
        __syncthreads();       // all threads past compute(it-1) before reuse
        if (it + 1 < NIT) {
            stage((it + 1) & 1, (it + 1) * BKt);  // overlaps compute(it)
            CP_COMMIT();
        }

        if (active) {
            const float* sa = Sa[it & 1];
            const float* sw = Sw[it & 1];

            #pragma unroll
            for (int kk = 0; kk < 2; kk++) {
                int kb = kk * 8;
                uint32_t bh[4][2], bl[4][2];
                #pragma unroll
                for (int nt = 0; nt < 4; nt++) {
                    int nr = wn + nt * 8 + g;
                    float w0 = sw[nr * SWd + kb + t];
                    float w1 = sw[nr * SWd + kb + t + 4];
                    float h0 = tf32f(w0), h1 = tf32f(w1);
                    bh[nt][0] = __float_as_uint(h0);
                    bh[nt][1] = __float_as_uint(h1);
                    bl[nt][0] = __float_as_uint(tf32f(w0 - h0));
                    bl[nt][1] = __float_as_uint(tf32f(w1 - h1));
                }
                #pragma unroll
                for (int mt = 0; mt < 4; mt++) {
                    int mr = wm + mt * 16 + g;
                    float a0 = sa[mr * SWd + kb + t];
                    float a1 = sa[(mr + 8) * SWd + kb + t];
                    float a2 = sa[mr * SWd + kb + t + 4];
                    float a3 = sa[(mr + 8) * SWd + kb + t + 4];
                    float h0 = tf32f(a0), h1 = tf32f(a1), h2 = tf32f(a2), h3 = tf32f(a3);
                    uint32_t ah[4], al[4];
                    ah[0] = __float_as_uint(h0); ah[1] = __float_as_uint(h1);
                    ah[2] = __float_as_uint(h2); ah[3] = __float_as_uint(h3);
                    al[0] = __float_as_uint(tf32f(a0 - h0));
                    al[1] = __float_as_uint(tf32f(a1 - h1));
                    al[2] = __float_as_uint(tf32f(a2 - h2));
                    al[3] = __float_as_uint(tf32f(a3 - h3));
                    #pragma unroll
                    for (int nt = 0; nt < 4; nt++) {
                        MMA_TF32(c[mt][nt], ah, bh[nt]);
                        MMA_TF32(c[mt][nt], ah, bl[nt]);
                        MMA_TF32(c[mt][nt], al, bh[nt]);
                    }
                }
            }
        }
    }

    // epilogue: store C + fused partial attention dots
    #pragma unroll
    for (int mt = 0; mt < 4; mt++) {
        int row = m0 + wm + mt * 16 + g;
        float ps = 0.f, pd = 0.f, qs = 0.f, qd = 0.f;
        #pragma unroll
        for (int nt = 0; nt < 4; nt++) {
            int cn = wn + nt * 8 + 2 * t;       // local col in [0,128)
            int col = n0 + cn;
            if (col < Dd) {
                if (row < Nn)
                    *(float2*)(C + (size_t)row * Dd + col) =
                        make_float2(c[mt][nt][0], c[mt][nt][1]);
                if (row + 8 < Nn)
                    *(float2*)(C + (size_t)(row + 8) * Dd + col) =
                        make_float2(c[mt][nt][2], c[mt][nt][3]);
            }
            float a0 = s_as[cn], a1 = s_as[cn + 1];
            float d0 = s_ad[cn], d1 = s_ad[cn + 1];
            ps += c[mt][nt][0] * a0 + c[mt][nt][1] * a1;
            pd += c[mt][nt][0] * d0 + c[mt][nt][1] * d1;
            qs += c[mt][nt][2] * a0 + c[mt][nt][3] * a1;
            qd += c[mt][nt][2] * d0 + c[mt][nt][3] * d1;
        }
        #pragma unroll
        for (int o = 1; o <= 2; o <<= 1) {
            ps += __shfl_xor_sync(0xffffffffu, ps, o);
            pd += __shfl_xor_sync(0xffffffffu, pd, o);
            qs += __shfl_xor_sync(0xffffffffu, qs, o);
            qd += __shfl_xor_sync(0xffffffffu, qd, o);
        }
        if (t == 0) {
            int i1 = wm + mt * 16 + g;
            int nw = wid & 3;
            s_pas[nw * 128 + i1] = ps;  s_pad[nw * 128 + i1] = pd;
            s_pas[nw * 128 + i1 + 8] = qs;  s_pad[nw * 128 + i1 + 8] = qd;
        }
    }
    __syncthreads();
    if (tid < 128) {
        int row = m0 + tid;
        if (row < Nn)
            g_asp[blockIdx.x][row] = s_pas[tid] + s_pas[128 + tid] +
                                     s_pas[256 + tid] + s_pas[384 + tid];
    } else {
        int i = tid - 128;
        int row = m0 + i;
        if (row < Nn)
            g_adp[blockIdx.x][row] = s_pad[i] + s_pad[128 + i] +
                                     s_pad[256 + i] + s_pad[384 + i];
    }
}

__global__ void combine_k() {
    int i = blockIdx.x * blockDim.x + threadIdx.x;
    if (i < Nn) {
        g_as[i] = g_asp[0][i] + g_asp[1][i] + g_asp[2][i];
        g_ad[i] = g_adp[0][i] + g_adp[1][i] + g_adp[2][i];
    }
}

// ---------------- fused edge softmax + aggregation (warp per dst) -----------
// mode 1 additionally computes the pooling score g_s.
__global__ void agg_k(const float* __restrict__ h,
                      const float* __restrict__ bias,
                      float* __restrict__ outp,
                      const int* __restrict__ batch, int mode) {
    int w = (blockIdx.x * blockDim.x + threadIdx.x) >> 5;
    int lane = threadIdx.x & 31;
    if (w >= Nn) return;
    int beg = g_rowptr[w], end = g_rowptr[w + 1];
    float ad = g_ad[w];

    // online softmax (max + denominator in one pass)
    float m = -3.4e38f, den = 0.f;
    for (int j = beg + lane; j < end; j += 32) {
        float e = lrelu(g_as[g_csrc[j]] + ad);
        if (e > m) { den = den * __expf(m - e) + 1.f; m = e; }
        else den += __expf(e - m);
    }
    #pragma unroll
    for (int o = 16; o; o >>= 1) {
        float mo = __shfl_xor_sync(0xffffffffu, m, o);
        float eo = __shfl_xor_sync(0xffffffffu, den, o);
        float mn = fmaxf(m, mo);
        den = den * __expf(m - mn) + eo * __expf(mo - mn);
        m = mn;
    }
    float inv = 1.f / den;

    float acc[10];
    #pragma unroll
    for (int i = 0; i < 10; i++) acc[i] = 0.f;

    for (int base = beg; base < end; base += 32) {
        int j = base + lane;
        float wt = 0.f; int src = 0;
        if (j < end) {
            src = g_csrc[j];
            wt = __expf(lrelu(g_as[src] + ad) - m) * inv;
        }
        int cnt = min(32, end - base);
        for (int u = 0; u < cnt; u++) {
            float wu = __shfl_sync(0xffffffffu, wt, u);
            int   su = __shfl_sync(0xffffffffu, src, u);
            const float* hr = h + (size_t)su * Dd;
            #pragma unroll
            for (int i = 0; i < 9; i++) acc[i] += wu * hr[lane + i * 32];
            int cc = lane + 288;
            if (cc < Dd) acc[9] += wu * hr[cc];
        }
    }

    if (mode == 0) {
        #pragma unroll
        for (int i = 0; i < 10; i++) {
            int cc = lane + i * 32;
            if (cc < Dd) {
                float v = acc[i] + bias[cc];
                outp[(size_t)w * Dd + cc] = v > 0.f ? v : 0.f;
            }
        }
    } else {
        int b = batch[w];
        const float* qr = g_qp + b * Dd;
        float s = 0.f;
        #pragma unroll
        for (int i = 0; i < 10; i++) {
            int cc = lane + i * 32;
            if (cc < Dd) {
                float v = acc[i] + bias[cc];
                v = v > 0.f ? v : 0.f;
                outp[(size_t)w * Dd + cc] = v;
                s += v * qr[cc];
            }
        }
        #pragma unroll
        for (int o = 16; o; o >>= 1) s += __shfl_xor_sync(0xffffffffu, s, o);
        if (lane == 0) g_s[w] = s * 0.04082482904638630f;  // 1/sqrt(600)
    }
}

// ---------------- qp = query @ attW  [B,D] ----------------------------------
__global__ void qp_k(const float* __restrict__ query, const float* __restrict__ attW) {
    int b = blockIdx.x;
    __shared__ float q[Qq];
    for (int i = threadIdx.x; i < Qq; i += blockDim.x) q[i] = query[(size_t)b * Qq + i];
    __syncthreads();
    for (int d = threadIdx.x; d < Dd; d += blockDim.x) {
        float acc = 0.f;
        for (int qi = 0; qi < Qq; qi++) acc += q[qi] * attW[(size_t)qi * Dd + d];
        g_qp[b * Dd + d] = acc;
    }
}

// ---------------- block-per-graph softmax pooling (batch is sorted) ---------
__global__ __launch_bounds__(256) void pool_k(const float* __restrict__ h,
                                              const int* __restrict__ batch) {
    int b = blockIdx.x;
    int tid = threadIdx.x, wid = tid >> 5, lane = tid & 31;
    __shared__ float red[256];
    __shared__ float s_acc[8][304];
    int start = lower_bound_i(batch, Nn, b);
    int end   = lower_bound_i(batch, Nn, b + 1);

    float m = -3.4e38f;
    for (int n = start + tid; n < end; n += 256) m = fmaxf(m, g_s[n]);
    red[tid] = m; __syncthreads();
    for (int o = 128; o; o >>= 1) { if (tid < o) red[tid] = fmaxf(red[tid], red[tid + o]); __syncthreads(); }
    m = red[0]; __syncthreads();

    float ds = 0.f;
    for (int n = start + tid; n < end; n += 256) ds += __expf(g_s[n] - m);
    red[tid] = ds; __syncthreads();
    for (int o = 128; o; o >>= 1) { if (tid < o) red[tid] += red[tid + o]; __syncthreads(); }
    float total = red[0];
    float inv = (total > 0.f) ? 1.f / total : 0.f;
    __syncthreads();

    float acc[10];
    #pragma unroll
    for (int i = 0; i < 10; i++) acc[i] = 0.f;
    for (int r = start + wid; r < end; r += 8) {
        float wt = __expf(g_s[r] - m) * inv;
        const float* hr = h + (size_t)r * Dd;
        #pragma unroll
        for (int i = 0; i < 9; i++) acc[i] += wt * hr[lane + i * 32];
        int cc = lane + 288;
        if (cc < Dd) acc[9] += wt * hr[cc];
    }
    #pragma unroll
    for (int i = 0; i < 10; i++) {
        int cc = lane + i * 32;
        if (cc < Dd) s_acc[wid][cc] = acc[i];
    }
    __syncthreads();
    for (int cc = tid; cc < Dd; cc += 256) {
        float v = 0.f;
        #pragma unroll
        for (int u = 0; u < 8; u++) v += s_acc[u][cc];
        g_pool[b * Dd + cc] = v > 0.f ? v : 0.f;   // ReLU fused
    }
}

// ---------------- final: out = relu(pooled) @ lin_w^T + lin_b ---------------
#define FINAL_SMEM (128 * 303 * 4)
__global__ __launch_bounds__(512) void final_k(const float* __restrict__ lin_w,
                                               const float* __restrict__ lin_b,
                                               float* __restrict__ out) {
    extern __shared__ float ps[];   // [128][303]
    int tid = threadIdx.x;
    for (int i = tid; i < Bb * Dd; i += 512) {
        int bb = i / Dd, k = i - bb * Dd;
        ps[bb * 303 + k] = g_pool[i];
    }
    __syncthreads();
    int w = tid >> 5, lane = tid & 31;
    int c = blockIdx.x * 16 + w;
    const float* wr = lin_w + (size_t)c * Dd;
    float a0 = 0.f, a1 = 0.f, a2 = 0.f, a3 = 0.f;
    for (int k = 0; k < Dd; k++) {
        float wv = wr[k];
        a0 += wv * ps[lane * 303 + k];
        a1 += wv * ps[(lane + 32) * 303 + k];
        a2 += wv * ps[(lane + 64) * 303 + k];
        a3 += wv * ps[(lane + 96) * 303 + k];
    }
    float lb = lin_b[c];
    out[(size_t)lane * Cc + c]        = a0 + lb;
    out[(size_t)(lane + 32) * Cc + c] = a1 + lb;
    out[(size_t)(lane + 64) * Cc + c] = a2 + lb;
    out[(size_t)(lane + 96) * Cc + c] = a3 + lb;
}

// ---------------- launch -----------------------------------------------------
extern "C" void kernel_launch(void* const* d_in, const int* in_sizes, int n_in,
                              void* d_out, int out_size) {
    const float* x        = (const float*)d_in[0];
    const int*   edges    = (const int*)  d_in[1];
    const float* query    = (const float*)d_in[2];
    const int*   batch    = (const int*)  d_in[3];
    const float* theta    = (const float*)d_in[4];
    const float* att_src  = (const float*)d_in[5];
    const float* att_dst  = (const float*)d_in[6];
    const float* gat_bias = (const float*)d_in[7];
    const float* attW     = (const float*)d_in[8];
    const float* lin_w    = (const float*)d_in[9];
    const float* lin_b    = (const float*)d_in[10];
    float* out = (float*)d_out;

    float *p_h, *p_o;
    cudaGetSymbolAddress((void**)&p_h, g_h);
    cudaGetSymbolAddress((void**)&p_o, g_o);

    cudaFuncSetAttribute(final_k, cudaFuncAttributeMaxDynamicSharedMemorySize, FINAL_SMEM);

    dim3 ggrid((Dd + BNt - 1) / BNt, (Nn + BMt - 1) / BMt);
    int wgrid = (Nn * 32 + 255) / 256;
    int cgrid = (Nn + 255) / 256;
    int sblk = (Nn + 255) / 256;   // 196 scan blocks

    // CSR build (parallel scan)
    zero_k<<<cgrid, 256>>>();
    count_k<<<(Ee + Nn + 255) / 256, 256>>>(edges);
    scan1_k<<<sblk, 256>>>();
    scan2_k<<<1, 256>>>(sblk);
    scan3_k<<<sblk, 256>>>();
    fill_k<<<(Ee + Nn + 255) / 256, 256>>>(edges);

    // layer 1 (input = raw x)
    gemm_mma_k<<<ggrid, 256>>>(x, theta, p_h, att_src, att_dst);
    combine_k<<<cgrid, 256>>>();
    agg_k<<<wgrid, 256>>>(p_h, gat_bias, p_o, batch, 0);
    // layer 2
    gemm_mma_k<<<ggrid, 256>>>(p_o, theta, p_h, att_src, att_dst);
    combine_k<<<cgrid, 256>>>();
    agg_k<<<wgrid, 256>>>(p_h, gat_bias, p_o, batch, 0);
    // layer 3 (fuses pooling score)
    gemm_mma_k<<<ggrid, 256>>>(p_o, theta, p_h, att_src, att_dst);
    combine_k<<<cgrid, 256>>>();
    qp_k<<<Bb, 384>>>(query, attW);
    agg_k<<<wgrid, 256>>>(p_h, gat_bias, p_o, batch, 1);

    pool_k<<<Bb, 256>>>(p_o, batch);
    final_k<<<Cc / 16, 512, FINAL_SMEM>>>(lin_w, lin_b, out);
}

// round 14
// speedup vs baseline: 2.0069x; 1.3761x over previous
#include <cuda_runtime.h>
#include <math.h>
#include <stdint.h>

#define Nn 50000
#define Ee 250000
#define Bb 128
#define Dd 302
#define Qq 600
#define Cc 2000
#define NEG_SLOPE 0.2f

// ---------------- scratch (device globals; no allocation allowed) ----------
__device__ float g_h[(size_t)Nn * Dd];     // GEMM output (pre-aggregation h)
__device__ float g_o[(size_t)Nn * Dd];     // agg output (next GEMM input / pooling)
__device__ float g_as[Nn], g_ad[Nn], g_s[Nn];
__device__ float g_asp[3][Nn], g_adp[3][Nn];
__device__ int   g_cnt[Nn];
__device__ int   g_cur[Nn];
__device__ int   g_rowptr[Nn + 1];
__device__ int   g_bsum[256];
__device__ int   g_csrc[Ee + Nn];
__device__ float g_qp[Bb * Dd];
__device__ float g_pool[Bb * Dd];

// ---------------- helpers ---------------------------------------------------
__device__ __forceinline__ float lrelu(float x) { return x > 0.f ? x : NEG_SLOPE * x; }

__device__ __forceinline__ int lower_bound_i(const int* a, int n, int v) {
    int lo = 0, hi = n;
    while (lo < hi) { int m = (lo + hi) >> 1; if (a[m] < v) lo = m + 1; else hi = m; }
    return lo;
}

// pack two fp32 -> bf16x2 (lo = first element / even k, hi = second / odd k)
__device__ __forceinline__ uint32_t packbf(float e0, float e1) {
    uint32_t r;
    asm("cvt.rn.bf16x2.f32 %0, %1, %2;" : "=r"(r) : "f"(e1), "f"(e0));
    return r;
}
// exact fp32 value of the bf16 halves
__device__ __forceinline__ float bflo(uint32_t r) { return __uint_as_float(r << 16); }
__device__ __forceinline__ float bfhi(uint32_t r) { return __uint_as_float(r & 0xffff0000u); }

#define MMA_BF16(cr, a, b) \
    asm volatile("mma.sync.aligned.m16n8k16.row.col.f32.bf16.bf16.f32 " \
        "{%0,%1,%2,%3}, {%4,%5,%6,%7}, {%8,%9}, {%0,%1,%2,%3};" \
        : "+f"((cr)[0]), "+f"((cr)[1]), "+f"((cr)[2]), "+f"((cr)[3]) \
        : "r"((a)[0]), "r"((a)[1]), "r"((a)[2]), "r"((a)[3]), \
          "r"((b)[0]), "r"((b)[1]))

#define CP_ASYNC8(dst_smem, src_ptr, sz) \
    asm volatile("cp.async.ca.shared.global [%0], [%1], 8, %2;" \
        :: "r"(dst_smem), "l"(src_ptr), "r"(sz))
#define CP_COMMIT() asm volatile("cp.async.commit_group;" ::: "memory")
#define CP_WAIT0()  asm volatile("cp.async.wait_group 0;" ::: "memory")

// ---------------- CSR build --------------------------------------------------
__global__ void zero_k() {
    int i = blockIdx.x * blockDim.x + threadIdx.x;
    if (i < Nn) { g_cnt[i] = 0; g_cur[i] = 0; }
}

__global__ void count_k(const int* __restrict__ edges) {
    int i = blockIdx.x * blockDim.x + threadIdx.x;
    if (i >= Ee + Nn) return;
    int dst = (i < Ee) ? edges[Ee + i] : (i - Ee);
    atomicAdd(&g_cnt[dst], 1);
}

__global__ void scan1_k() {
    __shared__ int sh[256];
    int tid = threadIdx.x;
    int i = blockIdx.x * 256 + tid;
    int v = (i < Nn) ? g_cnt[i] : 0;
    sh[tid] = v;
    __syncthreads();
    #pragma unroll
    for (int off = 1; off < 256; off <<= 1) {
        int t = (tid >= off) ? sh[tid - off] : 0;
        __syncthreads();
        sh[tid] += t;
        __syncthreads();
    }
    if (i <= Nn) g_rowptr[i] = sh[tid] - v;
    if (tid == 255) g_bsum[blockIdx.x] = sh[255];
}

__global__ void scan2_k(int nblk) {
    __shared__ int sh[256];
    int tid = threadIdx.x;
    int v = (tid < nblk) ? g_bsum[tid] : 0;
    sh[tid] = v;
    __syncthreads();
    #pragma unroll
    for (int off = 1; off < 256; off <<= 1) {
        int t = (tid >= off) ? sh[tid - off] : 0;
        __syncthreads();
        sh[tid] += t;
        __syncthreads();
    }
    if (tid < nblk) g_bsum[tid] = sh[tid] - v;
    if (tid == 255) g_rowptr[Nn] = sh[255];
}

__global__ void scan3_k() {
    int i = blockIdx.x * 256 + threadIdx.x;
    if (i < Nn) g_rowptr[i] += g_bsum[blockIdx.x];
}

__global__ void fill_k(const int* __restrict__ edges) {
    int i = blockIdx.x * blockDim.x + threadIdx.x;
    if (i >= Ee + Nn) return;
    int src, dst;
    if (i < Ee) { src = edges[i]; dst = edges[Ee + i]; }
    else        { src = dst = i - Ee; }
    int p = g_rowptr[dst] + atomicAdd(&g_cur[dst], 1);
    g_csrc[p] = src;
}

// ---------------- bf16 split mma GEMM ---------------------------------------
// C[M,302] = A[M,302] @ theta[302,302]^T. CTA tile 128x128x16, cp.async
// double-buffered, static smem 48KB (2 CTA/SM). 8 warps = 2(m) x 4(n);
// warp tile 64x32. m16n8k16 bf16, 3-term hi/lo split (ah*bh+ah*bl+al*bh).
// Row stride 24 floats -> conflict-free LDS.64 fragment loads.
// Fully-OOB n-warps skip MMA. Epilogue fuses attention dots (aliased smem).
#define BMt 128
#define BNt 128
#define BKt 16
#define SWd 24
#define NIT 19              // ceil(302/16)
#define STGF (BMt * SWd)    // 3072 floats per stage buffer

__global__ __launch_bounds__(256, 2) void gemm_mma_k(const float* __restrict__ A,
                                                     const float* __restrict__ W,
                                                     float* __restrict__ C,
                                                     const float* __restrict__ att_s,
                                                     const float* __restrict__ att_d) {
    __shared__ float pool[4 * STGF];   // 49152 B: [SA0 SA1 SW0 SW1]; epilogue aliases
    float* SA = pool;                  // [2][STGF]
    float* SW = pool + 2 * STGF;       // [2][STGF]

    int tid = threadIdx.x;
    int wid = tid >> 5, lane = tid & 31;
    int g = lane >> 2, t = lane & 3;
    int m0 = blockIdx.y * BMt, n0 = blockIdx.x * BNt;
    int wm = (wid >> 2) * 64;
    int wn = (wid & 3) * 32;
    const bool active = (n0 + wn) < Dd;   // warp-uniform column validity

    float c[4][4][4];
    #pragma unroll
    for (int i = 0; i < 4; i++)
        #pragma unroll
        for (int j = 0; j < 4; j++)
            #pragma unroll
            for (int f = 0; f < 4; f++) c[i][j][f] = 0.f;

    int srow = tid >> 3;   // 0..31
    int sc2  = tid & 7;    // float2 column index (k offset = 2*sc2)

    auto stage = [&](int s, int k0) {
        #pragma unroll
        for (int e = 0; e < 4; e++) {
            int row = srow + e * 32;
            int gm = m0 + row, gk = k0 + 2 * sc2;
            bool ok = (gm < Nn) && (gk < Dd);
            const float* src = ok ? (A + (size_t)gm * Dd + gk) : A;
            uint32_t dst = (uint32_t)__cvta_generic_to_shared(&SA[s * STGF + row * SWd + 2 * sc2]);
            CP_ASYNC8(dst, src, ok ? 8u : 0u);
        }
        #pragma unroll
        for (int e = 0; e < 4; e++) {
            int row = srow + e * 32;
            int gn = n0 + row, gk = k0 + 2 * sc2;
            bool ok = (gn < Dd) && (gk < Dd);
            const float* src = ok ? (W + (size_t)gn * Dd + gk) : W;
            uint32_t dst = (uint32_t)__cvta_generic_to_shared(&SW[s * STGF + row * SWd + 2 * sc2]);
            CP_ASYNC8(dst, src, ok ? 8u : 0u);
        }
    };

    stage(0, 0);
    CP_COMMIT();

    for (int it = 0; it < NIT; it++) {
        CP_WAIT0();
        __syncthreads();
        if (it + 1 < NIT) {
            stage((it + 1) & 1, (it + 1) * BKt);
            CP_COMMIT();
        }

        if (active) {
            const float* sa = SA + (it & 1) * STGF;
            const float* sw = SW + (it & 1) * STGF;

            uint32_t bh[4][2], bl[4][2];
            #pragma unroll
            for (int nt = 0; nt < 4; nt++) {
                int nr = wn + nt * 8 + g;
                float2 b0 = *(const float2*)&sw[nr * SWd + 2 * t];
                float2 b1 = *(const float2*)&sw[nr * SWd + 2 * t + 8];
                uint32_t h0 = packbf(b0.x, b0.y);
                uint32_t h1 = packbf(b1.x, b1.y);
                bh[nt][0] = h0;
                bh[nt][1] = h1;
                bl[nt][0] = packbf(b0.x - bflo(h0), b0.y - bfhi(h0));
                bl[nt][1] = packbf(b1.x - bflo(h1), b1.y - bfhi(h1));
            }
            #pragma unroll
            for (int mt = 0; mt < 4; mt++) {
                int mr = wm + mt * 16 + g;
                float2 A0 = *(const float2*)&sa[mr * SWd + 2 * t];
                float2 A1 = *(const float2*)&sa[(mr + 8) * SWd + 2 * t];
                float2 A2 = *(const float2*)&sa[mr * SWd + 2 * t + 8];
                float2 A3 = *(const float2*)&sa[(mr + 8) * SWd + 2 * t + 8];
                uint32_t ah[4], al[4];
                ah[0] = packbf(A0.x, A0.y);
                ah[1] = packbf(A1.x, A1.y);
                ah[2] = packbf(A2.x, A2.y);
                ah[3] = packbf(A3.x, A3.y);
                al[0] = packbf(A0.x - bflo(ah[0]), A0.y - bfhi(ah[0]));
                al[1] = packbf(A1.x - bflo(ah[1]), A1.y - bfhi(ah[1]));
                al[2] = packbf(A2.x - bflo(ah[2]), A2.y - bfhi(ah[2]));
                al[3] = packbf(A3.x - bflo(ah[3]), A3.y - bfhi(ah[3]));
                #pragma unroll
                for (int nt = 0; nt < 4; nt++) {
                    MMA_BF16(c[mt][nt], ah, bh[nt]);
                    MMA_BF16(c[mt][nt], ah, bl[nt]);
                    MMA_BF16(c[mt][nt], al, bh[nt]);
                }
            }
        }
    }

    // epilogue: alias the stage buffers for attention vectors + partial sums
    __syncthreads();                 // mainloop smem reads complete
    float* s_as  = pool;             // [128]
    float* s_ad  = pool + 128;       // [128]
    float* s_pas = pool + 256;       // [512]
    float* s_pad = pool + 768;       // [512]
    if (tid < 128) {
        int cidx = n0 + tid;
        s_as[tid] = (cidx < Dd) ? att_s[cidx] : 0.f;
        s_ad[tid] = (cidx < Dd) ? att_d[cidx] : 0.f;
    }
    __syncthreads();

    #pragma unroll
    for (int mt = 0; mt < 4; mt++) {
        int row = m0 + wm + mt * 16 + g;
        float ps = 0.f, pd = 0.f, qs = 0.f, qd = 0.f;
        #pragma unroll
        for (int nt = 0; nt < 4; nt++) {
            int cn = wn + nt * 8 + 2 * t;       // local col in [0,128)
            int col = n0 + cn;
            if (col < Dd) {
                if (row < Nn)
                    *(float2*)(C + (size_t)row * Dd + col) =
                        make_float2(c[mt][nt][0], c[mt][nt][1]);
                if (row + 8 < Nn)
                    *(float2*)(C + (size_t)(row + 8) * Dd + col) =
                        make_float2(c[mt][nt][2], c[mt][nt][3]);
            }
            float a0 = s_as[cn], a1 = s_as[cn + 1];
            float d0 = s_ad[cn], d1 = s_ad[cn + 1];
            ps += c[mt][nt][0] * a0 + c[mt][nt][1] * a1;
            pd += c[mt][nt][0] * d0 + c[mt][nt][1] * d1;
            qs += c[mt][nt][2] * a0 + c[mt][nt][3] * a1;
            qd += c[mt][nt][2] * d0 + c[mt][nt][3] * d1;
        }
        #pragma unroll
        for (int o = 1; o <= 2; o <<= 1) {
            ps += __shfl_xor_sync(0xffffffffu, ps, o);
            pd += __shfl_xor_sync(0xffffffffu, pd, o);
            qs += __shfl_xor_sync(0xffffffffu, qs, o);
            qd += __shfl_xor_sync(0xffffffffu, qd, o);
        }
        if (t == 0) {
            int i1 = wm + mt * 16 + g;
            int nw = wid & 3;
            s_pas[nw * 128 + i1] = ps;  s_pad[nw * 128 + i1] = pd;
            s_pas[nw * 128 + i1 + 8] = qs;  s_pad[nw * 128 + i1 + 8] = qd;
        }
    }
    __syncthreads();
    if (tid < 128) {
        int row = m0 + tid;
        if (row < Nn)
            g_asp[blockIdx.x][row] = s_pas[tid] + s_pas[128 + tid] +
                                     s_pas[256 + tid] + s_pas[384 + tid];
    } else {
        int i = tid - 128;
        int row = m0 + i;
        if (row < Nn)
            g_adp[blockIdx.x][row] = s_pad[i] + s_pad[128 + i] +
                                     s_pad[256 + i] + s_pad[384 + i];
    }
}

__global__ void combine_k() {
    int i = blockIdx.x * blockDim.x + threadIdx.x;
    if (i < Nn) {
        g_as[i] = g_asp[0][i] + g_asp[1][i] + g_asp[2][i];
        g_ad[i] = g_adp[0][i] + g_adp[1][i] + g_adp[2][i];
    }
}

// ---------------- fused edge softmax + aggregation (warp per dst) -----------
__global__ void agg_k(const float* __restrict__ h,
                      const float* __restrict__ bias,
                      float* __restrict__ outp,
                      const int* __restrict__ batch, int mode) {
    int w = (blockIdx.x * blockDim.x + threadIdx.x) >> 5;
    int lane = threadIdx.x & 31;
    if (w >= Nn) return;
    int beg = g_rowptr[w], end = g_rowptr[w + 1];
    float ad = g_ad[w];

    float m = -3.4e38f, den = 0.f;
    for (int j = beg + lane; j < end; j += 32) {
        float e = lrelu(g_as[g_csrc[j]] + ad);
        if (e > m) { den = den * __expf(m - e) + 1.f; m = e; }
        else den += __expf(e - m);
    }
    #pragma unroll
    for (int o = 16; o; o >>= 1) {
        float mo = __shfl_xor_sync(0xffffffffu, m, o);
        float eo = __shfl_xor_sync(0xffffffffu, den, o);
        float mn = fmaxf(m, mo);
        den = den * __expf(m - mn) + eo * __expf(mo - mn);
        m = mn;
    }
    float inv = 1.f / den;

    float acc[10];
    #pragma unroll
    for (int i = 0; i < 10; i++) acc[i] = 0.f;

    for (int base = beg; base < end; base += 32) {
        int j = base + lane;
        float wt = 0.f; int src = 0;
        if (j < end) {
            src = g_csrc[j];
            wt = __expf(lrelu(g_as[src] + ad) - m) * inv;
        }
        int cnt = min(32, end - base);
        for (int u = 0; u < cnt; u++) {
            float wu = __shfl_sync(0xffffffffu, wt, u);
            int   su = __shfl_sync(0xffffffffu, src, u);
            const float* hr = h + (size_t)su * Dd;
            #pragma unroll
            for (int i = 0; i < 9; i++) acc[i] += wu * hr[lane + i * 32];
            int cc = lane + 288;
            if (cc < Dd) acc[9] += wu * hr[cc];
        }
    }

    if (mode == 0) {
        #pragma unroll
        for (int i = 0; i < 10; i++) {
            int cc = lane + i * 32;
            if (cc < Dd) {
                float v = acc[i] + bias[cc];
                outp[(size_t)w * Dd + cc] = v > 0.f ? v : 0.f;
            }
        }
    } else {
        int b = batch[w];
        const float* qr = g_qp + b * Dd;
        float s = 0.f;
        #pragma unroll
        for (int i = 0; i < 10; i++) {
            int cc = lane + i * 32;
            if (cc < Dd) {
                float v = acc[i] + bias[cc];
                v = v > 0.f ? v : 0.f;
                outp[(size_t)w * Dd + cc] = v;
                s += v * qr[cc];
            }
        }
        #pragma unroll
        for (int o = 16; o; o >>= 1) s += __shfl_xor_sync(0xffffffffu, s, o);
        if (lane == 0) g_s[w] = s * 0.04082482904638630f;  // 1/sqrt(600)
    }
}

// ---------------- qp = query @ attW  [B,D] ----------------------------------
__global__ void qp_k(const float* __restrict__ query, const float* __restrict__ attW) {
    int b = blockIdx.x;
    __shared__ float q[Qq];
    for (int i = threadIdx.x; i < Qq; i += blockDim.x) q[i] = query[(size_t)b * Qq + i];
    __syncthreads();
    for (int d = threadIdx.x; d < Dd; d += blockDim.x) {
        float acc = 0.f;
        for (int qi = 0; qi < Qq; qi++) acc += q[qi] * attW[(size_t)qi * Dd + d];
        g_qp[b * Dd + d] = acc;
    }
}

// ---------------- block-per-graph softmax pooling (batch is sorted) ---------
__global__ __launch_bounds__(256) void pool_k(const float* __restrict__ h,
                                              const int* __restrict__ batch) {
    int b = blockIdx.x;
    int tid = threadIdx.x, wid = tid >> 5, lane = tid & 31;
    __shared__ float red[256];
    __shared__ float s_acc[8][304];
    int start = lower_bound_i(batch, Nn, b);
    int end   = lower_bound_i(batch, Nn, b + 1);

    float m = -3.4e38f;
    for (int n = start + tid; n < end; n += 256) m = fmaxf(m, g_s[n]);
    red[tid] = m; __syncthreads();
    for (int o = 128; o; o >>= 1) { if (tid < o) red[tid] = fmaxf(red[tid], red[tid + o]); __syncthreads(); }
    m = red[0]; __syncthreads();

    float ds = 0.f;
    for (int n = start + tid; n < end; n += 256) ds += __expf(g_s[n] - m);
    red[tid] = ds; __syncthreads();
    for (int o = 128; o; o >>= 1) { if (tid < o) red[tid] += red[tid + o]; __syncthreads(); }
    float total = red[0];
    float inv = (total > 0.f) ? 1.f / total : 0.f;
    __syncthreads();

    float acc[10];
    #pragma unroll
    for (int i = 0; i < 10; i++) acc[i] = 0.f;
    for (int r = start + wid; r < end; r += 8) {
        float wt = __expf(g_s[r] - m) * inv;
        const float* hr = h + (size_t)r * Dd;
        #pragma unroll
        for (int i = 0; i < 9; i++) acc[i] += wt * hr[lane + i * 32];
        int cc = lane + 288;
        if (cc < Dd) acc[9] += wt * hr[cc];
    }
    #pragma unroll
    for (int i = 0; i < 10; i++) {
        int cc = lane + i * 32;
        if (cc < Dd) s_acc[wid][cc] = acc[i];
    }
    __syncthreads();
    for (int cc = tid; cc < Dd; cc += 256) {
        float v = 0.f;
        #pragma unroll
        for (int u = 0; u < 8; u++) v += s_acc[u][cc];
        g_pool[b * Dd + cc] = v > 0.f ? v : 0.f;   // ReLU fused
    }
}

// ---------------- final: out = relu(pooled) @ lin_w^T + lin_b ---------------
#define FINAL_SMEM (128 * 303 * 4)
__global__ __launch_bounds__(512) void final_k(const float* __restrict__ lin_w,
                                               const float* __restrict__ lin_b,
                                               float* __restrict__ out) {
    extern __shared__ float ps[];   // [128][303]
    int tid = threadIdx.x;
    for (int i = tid; i < Bb * Dd; i += 512) {
        int bb = i / Dd, k = i - bb * Dd;
        ps[bb * 303 + k] = g_pool[i];
    }
    __syncthreads();
    int w = tid >> 5, lane = tid & 31;
    int c = blockIdx.x * 16 + w;
    const float* wr = lin_w + (size_t)c * Dd;
    float a0 = 0.f, a1 = 0.f, a2 = 0.f, a3 = 0.f;
    for (int k = 0; k < Dd; k++) {
        float wv = wr[k];
        a0 += wv * ps[lane * 303 + k];
        a1 += wv * ps[(lane + 32) * 303 + k];
        a2 += wv * ps[(lane + 64) * 303 + k];
        a3 += wv * ps[(lane + 96) * 303 + k];
    }
    float lb = lin_b[c];
    out[(size_t)lane * Cc + c]        = a0 + lb;
    out[(size_t)(lane + 32) * Cc + c] = a1 + lb;
    out[(size_t)(lane + 64) * Cc + c] = a2 + lb;
    out[(size_t)(lane + 96) * Cc + c] = a3 + lb;
}

// ---------------- launch -----------------------------------------------------
extern "C" void kernel_launch(void* const* d_in, const int* in_sizes, int n_in,
                              void* d_out, int out_size) {
    const float* x        = (const float*)d_in[0];
    const int*   edges    = (const int*)  d_in[1];
    const float* query    = (const float*)d_in[2];
    const int*   batch    = (const int*)  d_in[3];
    const float* theta    = (const float*)d_in[4];
    const float* att_src  = (const float*)d_in[5];
    const float* att_dst  = (const float*)d_in[6];
    const float* gat_bias = (const float*)d_in[7];
    const float* attW     = (const float*)d_in[8];
    const float* lin_w    = (const float*)d_in[9];
    const float* lin_b    = (const float*)d_in[10];
    float* out = (float*)d_out;

    float *p_h, *p_o;
    cudaGetSymbolAddress((void**)&p_h, g_h);
    cudaGetSymbolAddress((void**)&p_o, g_o);

    cudaFuncSetAttribute(final_k, cudaFuncAttributeMaxDynamicSharedMemorySize, FINAL_SMEM);

    dim3 ggrid((Dd + BNt - 1) / BNt, (Nn + BMt - 1) / BMt);
    int wgrid = (Nn * 32 + 255) / 256;
    int cgrid = (Nn + 255) / 256;
    int sblk = (Nn + 255) / 256;

    // CSR build (parallel scan)
    zero_k<<<cgrid, 256>>>();
    count_k<<<(Ee + Nn + 255) / 256, 256>>>(edges);
    scan1_k<<<sblk, 256>>>();
    scan2_k<<<1, 256>>>(sblk);
    scan3_k<<<sblk, 256>>>();
    fill_k<<<(Ee + Nn + 255) / 256, 256>>>(edges);

    // layer 1 (input = raw x)
    gemm_mma_k<<<ggrid, 256>>>(x, theta, p_h, att_src, att_dst);
    combine_k<<<cgrid, 256>>>();
    agg_k<<<wgrid, 256>>>(p_h, gat_bias, p_o, batch, 0);
    // layer 2
    gemm_mma_k<<<ggrid, 256>>>(p_o, theta, p_h, att_src, att_dst);
    combine_k<<<cgrid, 256>>>();
    agg_k<<<wgrid, 256>>>(p_h, gat_bias, p_o, batch, 0);
    // layer 3 (fuses pooling score)
    gemm_mma_k<<<ggrid, 256>>>(p_o, theta, p_h, att_src, att_dst);
    combine_k<<<cgrid, 256>>>();
    qp_k<<<Bb, 384>>>(query, attW);
    agg_k<<<wgrid, 256>>>(p_h, gat_bias, p_o, batch, 1);

    pool_k<<<Bb, 256>>>(p_o, batch);
    final_k<<<Cc / 16, 512, FINAL_SMEM>>>(lin_w, lin_b, out);
}